// round 9
// baseline (speedup 1.0000x reference)
#include <cuda_runtime.h>
#include <cuda_bf16.h>
#include <stdint.h>
#include <math.h>

#define SEQ 4096
#define E   2048

// ---------------------------------------------------------------------------
// Scratch (__device__ globals per allocation-free rule)
// ---------------------------------------------------------------------------
__device__ __nv_bfloat16 g_xh [SEQ * E], g_xl [SEQ * E];
__device__ __nv_bfloat16 g_Wqh[E * E],   g_Wql[E * E];
__device__ __nv_bfloat16 g_Wkh[E * E],   g_Wkl[E * E];
__device__ __nv_bfloat16 g_Wvh[E * E],   g_Wvl[E * E];
__device__ __nv_bfloat16 g_qh [SEQ * E], g_ql [SEQ * E];
__device__ __nv_bfloat16 g_kh [SEQ * E], g_kl [SEQ * E];
__device__ __nv_bfloat16 g_vTh[E * SEQ], g_vTl[E * SEQ];
__device__ float         g_s  [(size_t)SEQ * SEQ];
__device__ __nv_bfloat16 g_wh [(size_t)SEQ * SEQ], g_wl[(size_t)SEQ * SEQ];

// ---------------------------------------------------------------------------
// PTX helpers (baseline ISA only: cp.async, ldmatrix, mma.sync)
// ---------------------------------------------------------------------------
__device__ __forceinline__ uint32_t smem_u32(const void* p) {
    uint32_t a;
    asm("{ .reg .u64 t; cvta.to.shared.u64 t, %1; cvt.u32.u64 %0, t; }" : "=r"(a) : "l"(p));
    return a;
}

#define CP_ASYNC_16(dst, src) \
    asm volatile("cp.async.cg.shared.global [%0], [%1], 16;" :: "r"(dst), "l"(src))
#define CP_ASYNC_COMMIT() asm volatile("cp.async.commit_group;" ::: "memory")
#define CP_ASYNC_WAIT(n)  asm volatile("cp.async.wait_group %0;" :: "n"(n) : "memory")

#define LDSM4(r, a) \
    asm volatile("ldmatrix.sync.aligned.m8n8.x4.shared.b16 {%0,%1,%2,%3}, [%4];" \
        : "=r"((r)[0]), "=r"((r)[1]), "=r"((r)[2]), "=r"((r)[3]) : "r"(a))

#define MMA16816(d, a, b0, b1) \
    asm volatile("mma.sync.aligned.m16n8k16.row.col.f32.bf16.bf16.f32 " \
        "{%0,%1,%2,%3}, {%4,%5,%6,%7}, {%8,%9}, {%0,%1,%2,%3};" \
        : "+f"((d)[0]), "+f"((d)[1]), "+f"((d)[2]), "+f"((d)[3]) \
        : "r"((a)[0]), "r"((a)[1]), "r"((a)[2]), "r"((a)[3]), "r"(b0), "r"(b1))

// SW64 swizzle: 64B rows, 16B chunks XOR'ed with row bits
__device__ __forceinline__ uint32_t sw64(uint32_t o) { return o ^ ((o >> 3) & 0x30); }

// ---------------------------------------------------------------------------
// bf16x3 GEMM core: C[M,N] = (Ah+Al)[M,K] * (Bh+Bl)[N,K]^T
// CTA tile 64(M) x 128(N), 128 threads (4 warps), BK=32,
// 4-stage cp.async pipeline (96KB smem -> 2 CTAs/SM), warp tile 64x32,
// 3 MMA passes (hh, hl, lh), fragment double-buffering.
// Two co-resident CTAs hide each other's barrier/wait bubbles.
// ---------------------------------------------------------------------------
#define BK           32
#define TILE_A_B     4096            // 64 rows x 64B
#define TILE_B_B     8192            // 128 rows x 64B
#define OFF_AL       TILE_A_B                      // 4096
#define OFF_BH       (2 * TILE_A_B)                // 8192
#define OFF_BL       (2 * TILE_A_B + TILE_B_B)     // 16384
#define STAGE_B      (2 * TILE_A_B + 2 * TILE_B_B) // 24576
#define STAGES       4
#define SMEM_TOTAL   (STAGES * STAGE_B)            // 98304

struct Loader {
    const __nv_bfloat16 *pAh, *pAl, *pBh, *pBl;  // row-adjusted base pointers
    uint32_t a0, a1;            // swizzled A offsets (2 x 16B)
    uint32_t b0, b1, b2, b3;    // swizzled B offsets (4 x 16B)
    int helem;                  // A element offset within row (0 or 16)
};

__device__ __forceinline__ void load_stage(uint32_t sb, int st, const Loader& L, int k0)
{
    const uint32_t s = sb + st * STAGE_B;
    const __nv_bfloat16* a0 = L.pAh + k0 + L.helem;
    const __nv_bfloat16* a1 = L.pAl + k0 + L.helem;
    const __nv_bfloat16* b0 = L.pBh + k0;
    const __nv_bfloat16* b1 = L.pBl + k0;
    CP_ASYNC_16(s + L.a0, a0);               CP_ASYNC_16(s + L.a1, a0 + 8);
    CP_ASYNC_16(s + OFF_AL + L.a0, a1);      CP_ASYNC_16(s + OFF_AL + L.a1, a1 + 8);
    CP_ASYNC_16(s + OFF_BH + L.b0, b0);      CP_ASYNC_16(s + OFF_BH + L.b1, b0 + 8);
    CP_ASYNC_16(s + OFF_BH + L.b2, b0 + 16); CP_ASYNC_16(s + OFF_BH + L.b3, b0 + 24);
    CP_ASYNC_16(s + OFF_BL + L.b0, b1);      CP_ASYNC_16(s + OFF_BL + L.b1, b1 + 8);
    CP_ASYNC_16(s + OFF_BL + L.b2, b1 + 16); CP_ASYNC_16(s + OFF_BL + L.b3, b1 + 24);
    CP_ASYNC_COMMIT();
}

struct Frags {
    uint32_t ah[4][4], al[4][4], bh[2][4], bl[2][4];
};

__device__ __forceinline__ void load_frags(Frags& f, uint32_t stb,
                                           uint32_t a_base, uint32_t b_base, int k16)
{
    #pragma unroll
    for (int mi = 0; mi < 4; ++mi) {
        const uint32_t off = a_base + (uint32_t)mi * 1024 + k16 * 32;
        LDSM4(f.ah[mi], stb + sw64(off));
        LDSM4(f.al[mi], stb + OFF_AL + sw64(off));
    }
    #pragma unroll
    for (int ng = 0; ng < 2; ++ng) {
        const uint32_t off = b_base + (uint32_t)ng * 1024 + k16 * 32;
        LDSM4(f.bh[ng], stb + OFF_BH + sw64(off));
        LDSM4(f.bl[ng], stb + OFF_BL + sw64(off));
    }
}

__device__ __forceinline__ void mma_group(float acc[4][4][4], const Frags& f)
{
    #pragma unroll
    for (int mi = 0; mi < 4; ++mi)
        #pragma unroll
        for (int ni = 0; ni < 4; ++ni) {
            const int ng = ni >> 1;
            const int sel = (ni & 1) * 2;
            float* d = acc[mi][ni];
            MMA16816(d, f.ah[mi], f.bh[ng][sel], f.bh[ng][sel + 1]);
            MMA16816(d, f.ah[mi], f.bl[ng][sel], f.bl[ng][sel + 1]);
            MMA16816(d, f.al[mi], f.bh[ng][sel], f.bh[ng][sel + 1]);
        }
}

__device__ __forceinline__ void gemm_core(
    const __nv_bfloat16* __restrict__ Ah, const __nv_bfloat16* __restrict__ Al,
    const __nv_bfloat16* __restrict__ Bh, const __nv_bfloat16* __restrict__ Bl,
    float* __restrict__ Cf, __nv_bfloat16* __restrict__ Ch, __nv_bfloat16* __restrict__ Cl,
    int N, int K, int bm, int bn)
{
    extern __shared__ __align__(1024) char smem[];
    const uint32_t sb = smem_u32(smem);

    const int tid  = threadIdx.x;      // 0..127
    const int lane = tid & 31;
    const int wid  = tid >> 5;         // 0..3
    const int wn   = wid * 32;         // warp n offset; warp m offset = 0

    Loader L;
    {
        const int arow  = tid >> 1;           // 0..63
        const int ahalf = (tid & 1) * 32;     // byte offset within 64B row
        uint32_t ao = (uint32_t)arow * 64 + ahalf;
        L.a0 = sw64(ao);
        L.a1 = sw64(ao + 16);
        L.helem = ahalf >> 1;
        L.pAh = Ah + (size_t)(bm + arow) * K;
        L.pAl = Al + (size_t)(bm + arow) * K;
        const uint32_t bo = (uint32_t)tid * 64;   // B row = tid (0..127)
        L.b0 = sw64(bo);      L.b1 = sw64(bo + 16);
        L.b2 = sw64(bo + 32); L.b3 = sw64(bo + 48);
        L.pBh = Bh + (size_t)(bn + tid) * K;
        L.pBl = Bl + (size_t)(bn + tid) * K;
    }

    const uint32_t a_base = (uint32_t)(lane & 15) * 64 + (lane >> 4) * 16;
    const uint32_t b_base = (uint32_t)(wn + (lane & 7) + ((lane >> 4) << 3)) * 64
                          + ((lane >> 3) & 1) * 16;

    float acc[4][4][4];
    #pragma unroll
    for (int i = 0; i < 4; ++i)
        #pragma unroll
        for (int j = 0; j < 4; ++j)
            #pragma unroll
            for (int r = 0; r < 4; ++r) acc[i][j][r] = 0.0f;

    const int nk = K / BK;

    load_stage(sb, 0, L, 0);
    load_stage(sb, 1, L, BK);
    load_stage(sb, 2, L, 2 * BK);

    CP_ASYNC_WAIT(2);
    __syncthreads();

    Frags fa, fb;
    load_frags(fa, sb, a_base, b_base, 0);    // stage 0, k16=0

    for (int i = 0; i < nk; ++i) {
        const uint32_t stb = sb + (i & 3) * STAGE_B;

        // slot A: prefetch this stage's k16=1 group, compute k16=0 group
        load_frags(fb, stb, a_base, b_base, 1);
        mma_group(acc, fa);

        // slot B: refill stage i+3 (overwrites buffer whose reads completed
        // before iteration i-1's barrier), advance, prefetch next k16=0 group
        if (i + 3 < nk) load_stage(sb, (i + 3) & 3, L, (i + 3) * BK);
        else            CP_ASYNC_COMMIT();
        CP_ASYNC_WAIT(2);
        __syncthreads();
        if (i + 1 < nk)
            load_frags(fa, sb + ((i + 1) & 3) * STAGE_B, a_base, b_base, 0);
        mma_group(acc, fb);
    }

    // ---- epilogue: fragment m16n8: (c0,c1)->row er, (c2,c3)->row er+8
    const int er = lane >> 2;
    const int ec = (lane & 3) * 2;
    #pragma unroll
    for (int mi = 0; mi < 4; ++mi)
        #pragma unroll
        for (int ni = 0; ni < 4; ++ni) {
            const int r0 = bm + mi * 16 + er;
            const int c0 = bn + wn + ni * 8 + ec;
            float* a = acc[mi][ni];
            if (Cf) {
                *(float2*)(Cf + (size_t)r0 * N + c0)       = make_float2(a[0], a[1]);
                *(float2*)(Cf + (size_t)(r0 + 8) * N + c0) = make_float2(a[2], a[3]);
            } else {
                #pragma unroll
                for (int h = 0; h < 2; ++h) {
                    float v0 = a[2 * h], v1 = a[2 * h + 1];
                    __nv_bfloat16 h0 = __float2bfloat16(v0);
                    __nv_bfloat16 h1 = __float2bfloat16(v1);
                    __nv_bfloat16 l0 = __float2bfloat16(v0 - __bfloat162float(h0));
                    __nv_bfloat16 l1 = __float2bfloat16(v1 - __bfloat162float(h1));
                    size_t off = (size_t)(r0 + 8 * h) * N + c0;
                    *(__nv_bfloat162*)(Ch + off) = __halves2bfloat162(h0, h1);
                    *(__nv_bfloat162*)(Cl + off) = __halves2bfloat162(l0, l1);
                }
            }
        }
}

// Generic 2D-grid GEMM kernel (s = q k^T and out = w vT^T)
__global__ __launch_bounds__(128, 2)
void gemm_bf16x3(const __nv_bfloat16* __restrict__ Ah, const __nv_bfloat16* __restrict__ Al,
                 const __nv_bfloat16* __restrict__ Bh, const __nv_bfloat16* __restrict__ Bl,
                 float* __restrict__ Cf,
                 __nv_bfloat16* __restrict__ Ch, __nv_bfloat16* __restrict__ Cl,
                 int N, int K)
{
    gemm_core(Ah, Al, Bh, Bl, Cf, Ch, Cl, N, K, blockIdx.y * 64, blockIdx.x * 128);
}

// Merged Q/K/V projection kernel: one launch, linear grid of 3072 CTAs.
//  [0,1024):    q  = x @ Wq^T   (M=SEQ: 64 m-tiles, N=E: 16 n-tiles)
//  [1024,2048): k  = x @ Wk^T
//  [2048,3072): vT = Wv @ x^T   (M=E: 32 m-tiles, N=SEQ: 32 n-tiles)
__global__ __launch_bounds__(128, 2)
void qkv_gemm(const __nv_bfloat16* __restrict__ xh,  const __nv_bfloat16* __restrict__ xl,
              const __nv_bfloat16* __restrict__ Wqh, const __nv_bfloat16* __restrict__ Wql,
              const __nv_bfloat16* __restrict__ Wkh, const __nv_bfloat16* __restrict__ Wkl,
              const __nv_bfloat16* __restrict__ Wvh, const __nv_bfloat16* __restrict__ Wvl,
              __nv_bfloat16* __restrict__ qh,  __nv_bfloat16* __restrict__ ql,
              __nv_bfloat16* __restrict__ kh,  __nv_bfloat16* __restrict__ kl,
              __nv_bfloat16* __restrict__ vTh, __nv_bfloat16* __restrict__ vTl)
{
    const int idx = blockIdx.x;
    const __nv_bfloat16 *Ah, *Al, *Bh, *Bl;
    __nv_bfloat16 *Ch, *Cl;
    int bm, bn, N;

    if (idx < 2048) {                      // Q or K
        const int j = idx & 1023;
        bn = (j & 15) * 128;
        bm = (j >> 4) * 64;
        N  = E;
        Ah = xh; Al = xl;
        if (idx < 1024) { Bh = Wqh; Bl = Wql; Ch = qh; Cl = ql; }
        else            { Bh = Wkh; Bl = Wkl; Ch = kh; Cl = kl; }
    } else {                               // vT
        const int j = idx - 2048;
        bn = (j & 31) * 128;
        bm = (j >> 5) * 64;
        N  = SEQ;
        Ah = Wvh; Al = Wvl; Bh = xh; Bl = xl; Ch = vTh; Cl = vTl;
    }
    gemm_core(Ah, Al, Bh, Bl, nullptr, Ch, Cl, N, E, bm, bn);
}

// ---------------------------------------------------------------------------
// Merged fp32 -> (bf16 hi, bf16 lo) conversion for x, Wq, Wk, Wv (one launch)
// ---------------------------------------------------------------------------
#define X4 (SEQ * E / 4)
#define W4 (E * E / 4)

__global__ void conv_all(const float* __restrict__ x,  const float* __restrict__ Wq,
                         const float* __restrict__ Wk, const float* __restrict__ Wv,
                         __nv_bfloat16* __restrict__ xh,  __nv_bfloat16* __restrict__ xl,
                         __nv_bfloat16* __restrict__ Wqh, __nv_bfloat16* __restrict__ Wql,
                         __nv_bfloat16* __restrict__ Wkh, __nv_bfloat16* __restrict__ Wkl,
                         __nv_bfloat16* __restrict__ Wvh, __nv_bfloat16* __restrict__ Wvl)
{
    int i = blockIdx.x * blockDim.x + threadIdx.x;
    const float* src; __nv_bfloat16 *hi, *lo; int off;
    if (i < X4)                 { src = x;  hi = xh;  lo = xl;  off = i; }
    else if (i < X4 + W4)       { src = Wq; hi = Wqh; lo = Wql; off = i - X4; }
    else if (i < X4 + 2 * W4)   { src = Wk; hi = Wkh; lo = Wkl; off = i - X4 - W4; }
    else if (i < X4 + 3 * W4)   { src = Wv; hi = Wvh; lo = Wvl; off = i - X4 - 2 * W4; }
    else return;

    float4 v = ((const float4*)src)[off];
    __nv_bfloat16 h0 = __float2bfloat16(v.x), h1 = __float2bfloat16(v.y);
    __nv_bfloat16 h2 = __float2bfloat16(v.z), h3 = __float2bfloat16(v.w);
    __nv_bfloat16 l0 = __float2bfloat16(v.x - __bfloat162float(h0));
    __nv_bfloat16 l1 = __float2bfloat16(v.y - __bfloat162float(h1));
    __nv_bfloat16 l2 = __float2bfloat16(v.z - __bfloat162float(h2));
    __nv_bfloat16 l3 = __float2bfloat16(v.w - __bfloat162float(h3));
    ((__nv_bfloat162*)hi)[2 * off]     = __halves2bfloat162(h0, h1);
    ((__nv_bfloat162*)hi)[2 * off + 1] = __halves2bfloat162(h2, h3);
    ((__nv_bfloat162*)lo)[2 * off]     = __halves2bfloat162(l0, l1);
    ((__nv_bfloat162*)lo)[2 * off + 1] = __halves2bfloat162(l2, l3);
}

// ---------------------------------------------------------------------------
// Row softmax: fp32 in, bf16 hi/lo out (fused split), scale fused
// ---------------------------------------------------------------------------
__inline__ __device__ float warp_max(float v) {
    #pragma unroll
    for (int o = 16; o > 0; o >>= 1) v = fmaxf(v, __shfl_xor_sync(0xffffffffu, v, o));
    return v;
}
__inline__ __device__ float warp_sum(float v) {
    #pragma unroll
    for (int o = 16; o > 0; o >>= 1) v += __shfl_xor_sync(0xffffffffu, v, o);
    return v;
}

__global__ __launch_bounds__(256)
void softmax_rows(const float* __restrict__ S,
                  __nv_bfloat16* __restrict__ Wh, __nv_bfloat16* __restrict__ Wl)
{
    const int   rowi  = blockIdx.x;
    const float* p    = S + (size_t)rowi * SEQ;
    const float scale = 0.022097086912079608f;  // 1/sqrt(2048)
    const int   tid   = threadIdx.x;
    const int   lane  = tid & 31;
    const int   wid   = tid >> 5;

    __shared__ float red[8];

    float v[16];
    float m = -1e30f;
    #pragma unroll
    for (int i = 0; i < 16; ++i) {
        v[i] = p[tid + i * 256] * scale;
        m = fmaxf(m, v[i]);
    }
    m = warp_max(m);
    if (lane == 0) red[wid] = m;
    __syncthreads();
    if (wid == 0) {
        float t = (lane < 8) ? red[lane] : -1e30f;
        t = warp_max(t);
        if (lane == 0) red[0] = t;
    }
    __syncthreads();
    m = red[0];
    __syncthreads();

    float sum = 0.0f;
    #pragma unroll
    for (int i = 0; i < 16; ++i) {
        v[i] = __expf(v[i] - m);
        sum += v[i];
    }
    sum = warp_sum(sum);
    if (lane == 0) red[wid] = sum;
    __syncthreads();
    if (wid == 0) {
        float t = (lane < 8) ? red[lane] : 0.0f;
        t = warp_sum(t);
        if (lane == 0) red[0] = t;
    }
    __syncthreads();
    const float inv = 1.0f / red[0];

    #pragma unroll
    for (int i = 0; i < 16; ++i) {
        float w = v[i] * inv;
        __nv_bfloat16 h = __float2bfloat16(w);
        __nv_bfloat16 l = __float2bfloat16(w - __bfloat162float(h));
        Wh[(size_t)rowi * SEQ + tid + i * 256] = h;
        Wl[(size_t)rowi * SEQ + tid + i * 256] = l;
    }
}

// ---------------------------------------------------------------------------
// kernel_launch
// ---------------------------------------------------------------------------
extern "C" void kernel_launch(void* const* d_in, const int* in_sizes, int n_in,
                              void* d_out, int out_size)
{
    const float* x  = (const float*)d_in[0];
    const float* Wq = (const float*)d_in[1];
    const float* Wk = (const float*)d_in[2];
    const float* Wv = (const float*)d_in[3];
    float* out = (float*)d_out;

    cudaFuncSetAttribute(gemm_bf16x3, cudaFuncAttributeMaxDynamicSharedMemorySize, SMEM_TOTAL);
    cudaFuncSetAttribute(qkv_gemm,    cudaFuncAttributeMaxDynamicSharedMemorySize, SMEM_TOTAL);

    __nv_bfloat16 *xh, *xl, *Wqh, *Wql, *Wkh, *Wkl, *Wvh, *Wvl;
    __nv_bfloat16 *qh, *ql, *kh, *kl, *vTh, *vTl, *wh, *wl;
    float* s;
    cudaGetSymbolAddress((void**)&xh,  g_xh);  cudaGetSymbolAddress((void**)&xl,  g_xl);
    cudaGetSymbolAddress((void**)&Wqh, g_Wqh); cudaGetSymbolAddress((void**)&Wql, g_Wql);
    cudaGetSymbolAddress((void**)&Wkh, g_Wkh); cudaGetSymbolAddress((void**)&Wkl, g_Wkl);
    cudaGetSymbolAddress((void**)&Wvh, g_Wvh); cudaGetSymbolAddress((void**)&Wvl, g_Wvl);
    cudaGetSymbolAddress((void**)&qh,  g_qh);  cudaGetSymbolAddress((void**)&ql,  g_ql);
    cudaGetSymbolAddress((void**)&kh,  g_kh);  cudaGetSymbolAddress((void**)&kl,  g_kl);
    cudaGetSymbolAddress((void**)&vTh, g_vTh); cudaGetSymbolAddress((void**)&vTl, g_vTl);
    cudaGetSymbolAddress((void**)&wh,  g_wh);  cudaGetSymbolAddress((void**)&wl,  g_wl);
    cudaGetSymbolAddress((void**)&s,   g_s);

    // split all fp32 inputs into bf16 hi/lo in one launch
    const int total4 = X4 + 3 * W4;
    conv_all<<<(total4 + 255) / 256, 256>>>(x, Wq, Wk, Wv,
                                            xh, xl, Wqh, Wql, Wkh, Wkl, Wvh, Wvl);

    // q, k, vT in ONE launch (3072 CTAs, 2 CTAs/SM)
    qkv_gemm<<<3072, 128, SMEM_TOTAL>>>(xh, xl, Wqh, Wql, Wkh, Wkl, Wvh, Wvl,
                                        qh, ql, kh, kl, vTh, vTl);

    // s = q @ k^T  [SEQ,SEQ] -> fp32   (grid: 32 n-tiles x 64 m-tiles)
    gemm_bf16x3<<<dim3(SEQ / 128, SEQ / 64), 128, SMEM_TOTAL>>>(
        qh, ql, kh, kl, s, nullptr, nullptr, SEQ, E);
    // w = softmax(s/sqrt(E)) -> bf16 hi/lo
    softmax_rows<<<SEQ, 256>>>(s, wh, wl);
    // out = w @ vT^T  [SEQ,E] -> fp32  (grid: 16 n-tiles x 64 m-tiles)
    gemm_bf16x3<<<dim3(E / 128, SEQ / 64), 128, SMEM_TOTAL>>>(
        wh, wl, vTh, vTl, out, nullptr, nullptr, E, SEQ);
}

// round 10
// speedup vs baseline: 1.5265x; 1.5265x over previous
#include <cuda_runtime.h>
#include <cuda_bf16.h>
#include <stdint.h>
#include <math.h>

#define SEQ 4096
#define E   2048

// ---------------------------------------------------------------------------
// Scratch (__device__ globals per allocation-free rule)
// ---------------------------------------------------------------------------
__device__ __nv_bfloat16 g_xh [SEQ * E], g_xl [SEQ * E];
__device__ __nv_bfloat16 g_Wqh[E * E],   g_Wql[E * E];
__device__ __nv_bfloat16 g_Wkh[E * E],   g_Wkl[E * E];
__device__ __nv_bfloat16 g_Wvh[E * E],   g_Wvl[E * E];
__device__ __nv_bfloat16 g_qh [SEQ * E], g_ql [SEQ * E];
__device__ __nv_bfloat16 g_kh [SEQ * E], g_kl [SEQ * E];
__device__ __nv_bfloat16 g_vTh[E * SEQ], g_vTl[E * SEQ];
__device__ float         g_s  [(size_t)SEQ * SEQ];
__device__ __nv_bfloat16 g_wh [(size_t)SEQ * SEQ], g_wl[(size_t)SEQ * SEQ];

// ---------------------------------------------------------------------------
// PTX helpers (baseline ISA only: cp.async, ldmatrix, mma.sync)
// ---------------------------------------------------------------------------
__device__ __forceinline__ uint32_t smem_u32(const void* p) {
    uint32_t a;
    asm("{ .reg .u64 t; cvta.to.shared.u64 t, %1; cvt.u32.u64 %0, t; }" : "=r"(a) : "l"(p));
    return a;
}

#define CP_ASYNC_16(dst, src) \
    asm volatile("cp.async.cg.shared.global [%0], [%1], 16;" :: "r"(dst), "l"(src))
#define CP_ASYNC_COMMIT() asm volatile("cp.async.commit_group;" ::: "memory")
#define CP_ASYNC_WAIT(n)  asm volatile("cp.async.wait_group %0;" :: "n"(n) : "memory")

#define LDSM4(r, a) \
    asm volatile("ldmatrix.sync.aligned.m8n8.x4.shared.b16 {%0,%1,%2,%3}, [%4];" \
        : "=r"((r)[0]), "=r"((r)[1]), "=r"((r)[2]), "=r"((r)[3]) : "r"(a))

#define MMA16816(d, a, b0, b1) \
    asm volatile("mma.sync.aligned.m16n8k16.row.col.f32.bf16.bf16.f32 " \
        "{%0,%1,%2,%3}, {%4,%5,%6,%7}, {%8,%9}, {%0,%1,%2,%3};" \
        : "+f"((d)[0]), "+f"((d)[1]), "+f"((d)[2]), "+f"((d)[3]) \
        : "r"((a)[0]), "r"((a)[1]), "r"((a)[2]), "r"((a)[3]), "r"(b0), "r"(b1))

// SW64 swizzle: 64B rows, 16B chunks XOR'ed with row bits
__device__ __forceinline__ uint32_t sw64(uint32_t o) { return o ^ ((o >> 3) & 0x30); }

// ---------------------------------------------------------------------------
// bf16x3 GEMM core: C[M,N] = (Ah+Al)[M,K] * (Bh+Bl)[N,K]^T
// 128x128 CTA tile, BK=32, 5-stage cp.async pipeline (160KB smem), 256 thr,
// warp tile 64x32, 3 MMA passes (hh, hl, lh), fragment double-buffering.
// ---------------------------------------------------------------------------
#define BK           32
#define TILE_B       8192            // 128 rows x 64B
#define OFF_AL       TILE_B
#define OFF_BH       (2 * TILE_B)
#define OFF_BL       (3 * TILE_B)
#define STAGE_B      (4 * TILE_B)    // 32768
#define STAGES       5
#define SMEM_TOTAL   (STAGES * STAGE_B)   // 163840

struct Loader {
    const __nv_bfloat16 *pAh, *pAl, *pBh, *pBl;
    uint32_t d0, d1;
    int lhalf_elem;
};

__device__ __forceinline__ void load_stage(uint32_t sb, int st, const Loader& L, int k0)
{
    uint32_t stb = sb + st * STAGE_B;
    const __nv_bfloat16* a0 = L.pAh + k0 + L.lhalf_elem;
    const __nv_bfloat16* a1 = L.pAl + k0 + L.lhalf_elem;
    const __nv_bfloat16* b0 = L.pBh + k0 + L.lhalf_elem;
    const __nv_bfloat16* b1 = L.pBl + k0 + L.lhalf_elem;
    CP_ASYNC_16(stb + L.d0, a0);            CP_ASYNC_16(stb + L.d1, a0 + 8);
    CP_ASYNC_16(stb + OFF_AL + L.d0, a1);   CP_ASYNC_16(stb + OFF_AL + L.d1, a1 + 8);
    CP_ASYNC_16(stb + OFF_BH + L.d0, b0);   CP_ASYNC_16(stb + OFF_BH + L.d1, b0 + 8);
    CP_ASYNC_16(stb + OFF_BL + L.d0, b1);   CP_ASYNC_16(stb + OFF_BL + L.d1, b1 + 8);
    CP_ASYNC_COMMIT();
}

struct Frags {
    uint32_t ah[4][4], al[4][4], bh[2][4], bl[2][4];
};

__device__ __forceinline__ void load_frags(Frags& f, uint32_t stb,
                                           uint32_t a_base, uint32_t b_base, int k16)
{
    #pragma unroll
    for (int mi = 0; mi < 4; ++mi) {
        const uint32_t off = a_base + (uint32_t)mi * 1024 + k16 * 32;
        LDSM4(f.ah[mi], stb + sw64(off));
        LDSM4(f.al[mi], stb + OFF_AL + sw64(off));
    }
    #pragma unroll
    for (int ng = 0; ng < 2; ++ng) {
        const uint32_t off = b_base + (uint32_t)ng * 1024 + k16 * 32;
        LDSM4(f.bh[ng], stb + OFF_BH + sw64(off));
        LDSM4(f.bl[ng], stb + OFF_BL + sw64(off));
    }
}

// Pass-major order: adjacent MMAs hit independent accumulators (16 per pass)
// instead of chaining hh->hl->lh on the same accumulator (HMMA RAW stalls).
__device__ __forceinline__ void mma_group(float acc[4][4][4], const Frags& f)
{
    #pragma unroll
    for (int mi = 0; mi < 4; ++mi)          // pass 1: Ah * Bh
        #pragma unroll
        for (int ni = 0; ni < 4; ++ni) {
            const int ng = ni >> 1, sel = (ni & 1) * 2;
            MMA16816(acc[mi][ni], f.ah[mi], f.bh[ng][sel], f.bh[ng][sel + 1]);
        }
    #pragma unroll
    for (int mi = 0; mi < 4; ++mi)          // pass 2: Ah * Bl
        #pragma unroll
        for (int ni = 0; ni < 4; ++ni) {
            const int ng = ni >> 1, sel = (ni & 1) * 2;
            MMA16816(acc[mi][ni], f.ah[mi], f.bl[ng][sel], f.bl[ng][sel + 1]);
        }
    #pragma unroll
    for (int mi = 0; mi < 4; ++mi)          // pass 3: Al * Bh
        #pragma unroll
        for (int ni = 0; ni < 4; ++ni) {
            const int ng = ni >> 1, sel = (ni & 1) * 2;
            MMA16816(acc[mi][ni], f.al[mi], f.bh[ng][sel], f.bh[ng][sel + 1]);
        }
}

__device__ __forceinline__ void gemm_core(
    const __nv_bfloat16* __restrict__ Ah, const __nv_bfloat16* __restrict__ Al,
    const __nv_bfloat16* __restrict__ Bh, const __nv_bfloat16* __restrict__ Bl,
    float* __restrict__ Cf, __nv_bfloat16* __restrict__ Ch, __nv_bfloat16* __restrict__ Cl,
    int N, int K, int bm, int bn)
{
    extern __shared__ __align__(1024) char smem[];
    const uint32_t sb = smem_u32(smem);

    const int tid  = threadIdx.x;
    const int lane = tid & 31;
    const int wid  = tid >> 5;

    const int wm = (wid & 1) * 64;
    const int wn = (wid >> 1) * 32;

    Loader L;
    {
        const int lrow  = tid >> 1;
        const int lhalf = (tid & 1) * 32;
        uint32_t o = (uint32_t)lrow * 64 + lhalf;
        L.d0 = sw64(o);
        L.d1 = sw64(o + 16);
        L.lhalf_elem = lhalf >> 1;
        L.pAh = Ah + (size_t)(bm + lrow) * K;
        L.pAl = Al + (size_t)(bm + lrow) * K;
        L.pBh = Bh + (size_t)(bn + lrow) * K;
        L.pBl = Bl + (size_t)(bn + lrow) * K;
    }

    const uint32_t a_base = (uint32_t)(wm + (lane & 15)) * 64 + (lane >> 4) * 16;
    const uint32_t b_base = (uint32_t)(wn + (lane & 7) + ((lane >> 4) << 3)) * 64
                          + ((lane >> 3) & 1) * 16;

    float acc[4][4][4];
    #pragma unroll
    for (int i = 0; i < 4; ++i)
        #pragma unroll
        for (int j = 0; j < 4; ++j)
            #pragma unroll
            for (int r = 0; r < 4; ++r) acc[i][j][r] = 0.0f;

    const int nk = K / BK;

    load_stage(sb, 0, L, 0);
    load_stage(sb, 1, L, BK);
    load_stage(sb, 2, L, 2 * BK);
    load_stage(sb, 3, L, 3 * BK);

    CP_ASYNC_WAIT(3);
    __syncthreads();

    Frags fa, fb;
    load_frags(fa, sb, a_base, b_base, 0);    // stage 0, k16=0

    int st = 0, stw = 4;   // current stage, write-target stage (i+4)%5
    for (int i = 0; i < nk; ++i) {
        const uint32_t stb = sb + st * STAGE_B;

        // slot A: prefetch this stage's k16=1 group, compute k16=0 group
        load_frags(fb, stb, a_base, b_base, 1);
        mma_group(acc, fa);

        // slot B: refill stage i+4, advance, prefetch next k16=0 group
        if (i + 4 < nk) load_stage(sb, stw, L, (i + 4) * BK);
        else            CP_ASYNC_COMMIT();
        CP_ASYNC_WAIT(3);
        __syncthreads();

        if (++st  == STAGES) st  = 0;
        if (++stw == STAGES) stw = 0;
        if (i + 1 < nk)
            load_frags(fa, sb + st * STAGE_B, a_base, b_base, 0);
        mma_group(acc, fb);
    }

    // ---- epilogue: fragment m16n8: (c0,c1)->row er, (c2,c3)->row er+8
    const int er = lane >> 2;
    const int ec = (lane & 3) * 2;
    #pragma unroll
    for (int mi = 0; mi < 4; ++mi)
        #pragma unroll
        for (int ni = 0; ni < 4; ++ni) {
            const int r0 = bm + wm + mi * 16 + er;
            const int c0 = bn + wn + ni * 8 + ec;
            float* a = acc[mi][ni];
            if (Cf) {
                *(float2*)(Cf + (size_t)r0 * N + c0)       = make_float2(a[0], a[1]);
                *(float2*)(Cf + (size_t)(r0 + 8) * N + c0) = make_float2(a[2], a[3]);
            } else {
                #pragma unroll
                for (int h = 0; h < 2; ++h) {
                    float v0 = a[2 * h], v1 = a[2 * h + 1];
                    __nv_bfloat16 h0 = __float2bfloat16(v0);
                    __nv_bfloat16 h1 = __float2bfloat16(v1);
                    __nv_bfloat16 l0 = __float2bfloat16(v0 - __bfloat162float(h0));
                    __nv_bfloat16 l1 = __float2bfloat16(v1 - __bfloat162float(h1));
                    size_t off = (size_t)(r0 + 8 * h) * N + c0;
                    *(__nv_bfloat162*)(Ch + off) = __halves2bfloat162(h0, h1);
                    *(__nv_bfloat162*)(Cl + off) = __halves2bfloat162(l0, l1);
                }
            }
        }
}

// Generic 2D-grid GEMM kernel (used for s = q k^T and out = w vT^T)
__global__ __launch_bounds__(256, 1)
void gemm_bf16x3(const __nv_bfloat16* __restrict__ Ah, const __nv_bfloat16* __restrict__ Al,
                 const __nv_bfloat16* __restrict__ Bh, const __nv_bfloat16* __restrict__ Bl,
                 float* __restrict__ Cf,
                 __nv_bfloat16* __restrict__ Ch, __nv_bfloat16* __restrict__ Cl,
                 int N, int K)
{
    gemm_core(Ah, Al, Bh, Bl, Cf, Ch, Cl, N, K, blockIdx.y * 128, blockIdx.x * 128);
}

// Merged Q/K/V projection kernel: one launch, linear grid of 1536 CTAs.
__global__ __launch_bounds__(256, 1)
void qkv_gemm(const __nv_bfloat16* __restrict__ xh,  const __nv_bfloat16* __restrict__ xl,
              const __nv_bfloat16* __restrict__ Wqh, const __nv_bfloat16* __restrict__ Wql,
              const __nv_bfloat16* __restrict__ Wkh, const __nv_bfloat16* __restrict__ Wkl,
              const __nv_bfloat16* __restrict__ Wvh, const __nv_bfloat16* __restrict__ Wvl,
              __nv_bfloat16* __restrict__ qh,  __nv_bfloat16* __restrict__ ql,
              __nv_bfloat16* __restrict__ kh,  __nv_bfloat16* __restrict__ kl,
              __nv_bfloat16* __restrict__ vTh, __nv_bfloat16* __restrict__ vTl)
{
    const int idx = blockIdx.x;
    const __nv_bfloat16 *Ah, *Al, *Bh, *Bl;
    __nv_bfloat16 *Ch, *Cl;
    int bm, bn, N;

    if (idx < 1024) {                      // Q or K: grid 16(n) x 32(m)
        const int j = idx & 511;
        bn = (j & 15) * 128;
        bm = (j >> 4) * 128;
        N  = E;
        Ah = xh; Al = xl;
        if (idx < 512) { Bh = Wqh; Bl = Wql; Ch = qh; Cl = ql; }
        else           { Bh = Wkh; Bl = Wkl; Ch = kh; Cl = kl; }
    } else {                               // vT: grid 32(n) x 16(m)
        const int j = idx - 1024;
        bn = (j & 31) * 128;
        bm = (j >> 5) * 128;
        N  = SEQ;
        Ah = Wvh; Al = Wvl; Bh = xh; Bl = xl; Ch = vTh; Cl = vTl;
    }
    gemm_core(Ah, Al, Bh, Bl, nullptr, Ch, Cl, N, E, bm, bn);
}

// ---------------------------------------------------------------------------
// Merged fp32 -> (bf16 hi, bf16 lo) conversion for x, Wq, Wk, Wv (one launch)
// ---------------------------------------------------------------------------
#define X4 (SEQ * E / 4)
#define W4 (E * E / 4)

__global__ void conv_all(const float* __restrict__ x,  const float* __restrict__ Wq,
                         const float* __restrict__ Wk, const float* __restrict__ Wv,
                         __nv_bfloat16* __restrict__ xh,  __nv_bfloat16* __restrict__ xl,
                         __nv_bfloat16* __restrict__ Wqh, __nv_bfloat16* __restrict__ Wql,
                         __nv_bfloat16* __restrict__ Wkh, __nv_bfloat16* __restrict__ Wkl,
                         __nv_bfloat16* __restrict__ Wvh, __nv_bfloat16* __restrict__ Wvl)
{
    int i = blockIdx.x * blockDim.x + threadIdx.x;
    const float* src; __nv_bfloat16 *hi, *lo; int off;
    if (i < X4)                 { src = x;  hi = xh;  lo = xl;  off = i; }
    else if (i < X4 + W4)       { src = Wq; hi = Wqh; lo = Wql; off = i - X4; }
    else if (i < X4 + 2 * W4)   { src = Wk; hi = Wkh; lo = Wkl; off = i - X4 - W4; }
    else if (i < X4 + 3 * W4)   { src = Wv; hi = Wvh; lo = Wvl; off = i - X4 - 2 * W4; }
    else return;

    float4 v = ((const float4*)src)[off];
    __nv_bfloat16 h0 = __float2bfloat16(v.x), h1 = __float2bfloat16(v.y);
    __nv_bfloat16 h2 = __float2bfloat16(v.z), h3 = __float2bfloat16(v.w);
    __nv_bfloat16 l0 = __float2bfloat16(v.x - __bfloat162float(h0));
    __nv_bfloat16 l1 = __float2bfloat16(v.y - __bfloat162float(h1));
    __nv_bfloat16 l2 = __float2bfloat16(v.z - __bfloat162float(h2));
    __nv_bfloat16 l3 = __float2bfloat16(v.w - __bfloat162float(h3));
    ((__nv_bfloat162*)hi)[2 * off]     = __halves2bfloat162(h0, h1);
    ((__nv_bfloat162*)hi)[2 * off + 1] = __halves2bfloat162(h2, h3);
    ((__nv_bfloat162*)lo)[2 * off]     = __halves2bfloat162(l0, l1);
    ((__nv_bfloat162*)lo)[2 * off + 1] = __halves2bfloat162(l2, l3);
}

// ---------------------------------------------------------------------------
// Row softmax: fp32 in, bf16 hi/lo out (fused split), scale fused
// ---------------------------------------------------------------------------
__inline__ __device__ float warp_max(float v) {
    #pragma unroll
    for (int o = 16; o > 0; o >>= 1) v = fmaxf(v, __shfl_xor_sync(0xffffffffu, v, o));
    return v;
}
__inline__ __device__ float warp_sum(float v) {
    #pragma unroll
    for (int o = 16; o > 0; o >>= 1) v += __shfl_xor_sync(0xffffffffu, v, o);
    return v;
}

__global__ __launch_bounds__(256)
void softmax_rows(const float* __restrict__ S,
                  __nv_bfloat16* __restrict__ Wh, __nv_bfloat16* __restrict__ Wl)
{
    const int   rowi  = blockIdx.x;
    const float* p    = S + (size_t)rowi * SEQ;
    const float scale = 0.022097086912079608f;  // 1/sqrt(2048)
    const int   tid   = threadIdx.x;
    const int   lane  = tid & 31;
    const int   wid   = tid >> 5;

    __shared__ float red[8];

    float v[16];
    float m = -1e30f;
    #pragma unroll
    for (int i = 0; i < 16; ++i) {
        v[i] = p[tid + i * 256] * scale;
        m = fmaxf(m, v[i]);
    }
    m = warp_max(m);
    if (lane == 0) red[wid] = m;
    __syncthreads();
    if (wid == 0) {
        float t = (lane < 8) ? red[lane] : -1e30f;
        t = warp_max(t);
        if (lane == 0) red[0] = t;
    }
    __syncthreads();
    m = red[0];
    __syncthreads();

    float sum = 0.0f;
    #pragma unroll
    for (int i = 0; i < 16; ++i) {
        v[i] = __expf(v[i] - m);
        sum += v[i];
    }
    sum = warp_sum(sum);
    if (lane == 0) red[wid] = sum;
    __syncthreads();
    if (wid == 0) {
        float t = (lane < 8) ? red[lane] : 0.0f;
        t = warp_sum(t);
        if (lane == 0) red[0] = t;
    }
    __syncthreads();
    const float inv = 1.0f / red[0];

    #pragma unroll
    for (int i = 0; i < 16; ++i) {
        float w = v[i] * inv;
        __nv_bfloat16 h = __float2bfloat16(w);
        __nv_bfloat16 l = __float2bfloat16(w - __bfloat162float(h));
        Wh[(size_t)rowi * SEQ + tid + i * 256] = h;
        Wl[(size_t)rowi * SEQ + tid + i * 256] = l;
    }
}

// ---------------------------------------------------------------------------
// kernel_launch
// ---------------------------------------------------------------------------
extern "C" void kernel_launch(void* const* d_in, const int* in_sizes, int n_in,
                              void* d_out, int out_size)
{
    const float* x  = (const float*)d_in[0];
    const float* Wq = (const float*)d_in[1];
    const float* Wk = (const float*)d_in[2];
    const float* Wv = (const float*)d_in[3];
    float* out = (float*)d_out;

    cudaFuncSetAttribute(gemm_bf16x3, cudaFuncAttributeMaxDynamicSharedMemorySize, SMEM_TOTAL);
    cudaFuncSetAttribute(qkv_gemm,    cudaFuncAttributeMaxDynamicSharedMemorySize, SMEM_TOTAL);

    __nv_bfloat16 *xh, *xl, *Wqh, *Wql, *Wkh, *Wkl, *Wvh, *Wvl;
    __nv_bfloat16 *qh, *ql, *kh, *kl, *vTh, *vTl, *wh, *wl;
    float* s;
    cudaGetSymbolAddress((void**)&xh,  g_xh);  cudaGetSymbolAddress((void**)&xl,  g_xl);
    cudaGetSymbolAddress((void**)&Wqh, g_Wqh); cudaGetSymbolAddress((void**)&Wql, g_Wql);
    cudaGetSymbolAddress((void**)&Wkh, g_Wkh); cudaGetSymbolAddress((void**)&Wkl, g_Wkl);
    cudaGetSymbolAddress((void**)&Wvh, g_Wvh); cudaGetSymbolAddress((void**)&Wvl, g_Wvl);
    cudaGetSymbolAddress((void**)&qh,  g_qh);  cudaGetSymbolAddress((void**)&ql,  g_ql);
    cudaGetSymbolAddress((void**)&kh,  g_kh);  cudaGetSymbolAddress((void**)&kl,  g_kl);
    cudaGetSymbolAddress((void**)&vTh, g_vTh); cudaGetSymbolAddress((void**)&vTl, g_vTl);
    cudaGetSymbolAddress((void**)&wh,  g_wh);  cudaGetSymbolAddress((void**)&wl,  g_wl);
    cudaGetSymbolAddress((void**)&s,   g_s);

    // split all fp32 inputs into bf16 hi/lo in one launch
    const int total4 = X4 + 3 * W4;
    conv_all<<<(total4 + 255) / 256, 256>>>(x, Wq, Wk, Wv,
                                            xh, xl, Wqh, Wql, Wkh, Wkl, Wvh, Wvl);

    // q, k, vT in ONE launch (1536 CTAs)
    qkv_gemm<<<1536, 256, SMEM_TOTAL>>>(xh, xl, Wqh, Wql, Wkh, Wkl, Wvh, Wvl,
                                        qh, ql, kh, kl, vTh, vTl);

    // s = q @ k^T  [SEQ,SEQ] -> fp32
    gemm_bf16x3<<<dim3(SEQ / 128, SEQ / 128), 256, SMEM_TOTAL>>>(
        qh, ql, kh, kl, s, nullptr, nullptr, SEQ, E);
    // w = softmax(s/sqrt(E)) -> bf16 hi/lo
    softmax_rows<<<SEQ, 256>>>(s, wh, wl);
    // out = w @ vT^T  [SEQ,E] -> fp32
    gemm_bf16x3<<<dim3(E / 128, SEQ / 128), 256, SMEM_TOTAL>>>(
        wh, wl, vTh, vTl, out, nullptr, nullptr, E, SEQ);
}

// round 11
// speedup vs baseline: 1.5585x; 1.0210x over previous
#include <cuda_runtime.h>
#include <cuda_bf16.h>
#include <stdint.h>
#include <math.h>

#define SEQ 4096
#define E   2048

// ---------------------------------------------------------------------------
// Scratch (__device__ globals per allocation-free rule)
// g_s doubles as: s logits (fp32, SEQ*SEQ) before softmax, then as the
// 2x split-K partial buffers (2 * SEQ * E fp32 = SEQ*SEQ) for the out-GEMM.
// ---------------------------------------------------------------------------
__device__ __nv_bfloat16 g_xh [SEQ * E], g_xl [SEQ * E];
__device__ __nv_bfloat16 g_Wqh[E * E],   g_Wql[E * E];
__device__ __nv_bfloat16 g_Wkh[E * E],   g_Wkl[E * E];
__device__ __nv_bfloat16 g_Wvh[E * E],   g_Wvl[E * E];
__device__ __nv_bfloat16 g_qh [SEQ * E], g_ql [SEQ * E];
__device__ __nv_bfloat16 g_kh [SEQ * E], g_kl [SEQ * E];
__device__ __nv_bfloat16 g_vTh[E * SEQ], g_vTl[E * SEQ];
__device__ float         g_s  [(size_t)SEQ * SEQ];
__device__ __nv_bfloat16 g_wh [(size_t)SEQ * SEQ], g_wl[(size_t)SEQ * SEQ];

// ---------------------------------------------------------------------------
// PTX helpers (baseline ISA only: cp.async, ldmatrix, mma.sync)
// ---------------------------------------------------------------------------
__device__ __forceinline__ uint32_t smem_u32(const void* p) {
    uint32_t a;
    asm("{ .reg .u64 t; cvta.to.shared.u64 t, %1; cvt.u32.u64 %0, t; }" : "=r"(a) : "l"(p));
    return a;
}

#define CP_ASYNC_16(dst, src) \
    asm volatile("cp.async.cg.shared.global [%0], [%1], 16;" :: "r"(dst), "l"(src))
#define CP_ASYNC_COMMIT() asm volatile("cp.async.commit_group;" ::: "memory")
#define CP_ASYNC_WAIT(n)  asm volatile("cp.async.wait_group %0;" :: "n"(n) : "memory")

#define LDSM4(r, a) \
    asm volatile("ldmatrix.sync.aligned.m8n8.x4.shared.b16 {%0,%1,%2,%3}, [%4];" \
        : "=r"((r)[0]), "=r"((r)[1]), "=r"((r)[2]), "=r"((r)[3]) : "r"(a))

#define MMA16816(d, a, b0, b1) \
    asm volatile("mma.sync.aligned.m16n8k16.row.col.f32.bf16.bf16.f32 " \
        "{%0,%1,%2,%3}, {%4,%5,%6,%7}, {%8,%9}, {%0,%1,%2,%3};" \
        : "+f"((d)[0]), "+f"((d)[1]), "+f"((d)[2]), "+f"((d)[3]) \
        : "r"((a)[0]), "r"((a)[1]), "r"((a)[2]), "r"((a)[3]), "r"(b0), "r"(b1))

// SW64 swizzle: 64B rows, 16B chunks XOR'ed with row bits
__device__ __forceinline__ uint32_t sw64(uint32_t o) { return o ^ ((o >> 3) & 0x30); }

// ---------------------------------------------------------------------------
// bf16x3 GEMM core: C[M,N] = (Ah+Al)[M,Ks(.sel K cols)] * (Bh+Bl)^T
// 128x128 CTA tile, BK=32, 5-stage cp.async pipeline (160KB smem), 256 thr,
// warp tile 64x32, 3 MMA passes (hh, hl, lh) in pass-major order,
// fragment double-buffering. Ks = operand row stride (== K except split-K).
// ---------------------------------------------------------------------------
#define BK           32
#define TILE_B       8192            // 128 rows x 64B
#define OFF_AL       TILE_B
#define OFF_BH       (2 * TILE_B)
#define OFF_BL       (3 * TILE_B)
#define STAGE_B      (4 * TILE_B)    // 32768
#define STAGES       5
#define SMEM_TOTAL   (STAGES * STAGE_B)   // 163840

struct Loader {
    const __nv_bfloat16 *pAh, *pAl, *pBh, *pBl;
    uint32_t d0, d1;
    int lhalf_elem;
};

__device__ __forceinline__ void load_stage(uint32_t sb, int st, const Loader& L, int k0)
{
    uint32_t stb = sb + st * STAGE_B;
    const __nv_bfloat16* a0 = L.pAh + k0 + L.lhalf_elem;
    const __nv_bfloat16* a1 = L.pAl + k0 + L.lhalf_elem;
    const __nv_bfloat16* b0 = L.pBh + k0 + L.lhalf_elem;
    const __nv_bfloat16* b1 = L.pBl + k0 + L.lhalf_elem;
    CP_ASYNC_16(stb + L.d0, a0);            CP_ASYNC_16(stb + L.d1, a0 + 8);
    CP_ASYNC_16(stb + OFF_AL + L.d0, a1);   CP_ASYNC_16(stb + OFF_AL + L.d1, a1 + 8);
    CP_ASYNC_16(stb + OFF_BH + L.d0, b0);   CP_ASYNC_16(stb + OFF_BH + L.d1, b0 + 8);
    CP_ASYNC_16(stb + OFF_BL + L.d0, b1);   CP_ASYNC_16(stb + OFF_BL + L.d1, b1 + 8);
    CP_ASYNC_COMMIT();
}

struct Frags {
    uint32_t ah[4][4], al[4][4], bh[2][4], bl[2][4];
};

__device__ __forceinline__ void load_frags(Frags& f, uint32_t stb,
                                           uint32_t a_base, uint32_t b_base, int k16)
{
    #pragma unroll
    for (int mi = 0; mi < 4; ++mi) {
        const uint32_t off = a_base + (uint32_t)mi * 1024 + k16 * 32;
        LDSM4(f.ah[mi], stb + sw64(off));
        LDSM4(f.al[mi], stb + OFF_AL + sw64(off));
    }
    #pragma unroll
    for (int ng = 0; ng < 2; ++ng) {
        const uint32_t off = b_base + (uint32_t)ng * 1024 + k16 * 32;
        LDSM4(f.bh[ng], stb + OFF_BH + sw64(off));
        LDSM4(f.bl[ng], stb + OFF_BL + sw64(off));
    }
}

// Pass-major order: adjacent MMAs hit independent accumulators (16 per pass).
__device__ __forceinline__ void mma_group(float acc[4][4][4], const Frags& f)
{
    #pragma unroll
    for (int mi = 0; mi < 4; ++mi)          // pass 1: Ah * Bh
        #pragma unroll
        for (int ni = 0; ni < 4; ++ni) {
            const int ng = ni >> 1, sel = (ni & 1) * 2;
            MMA16816(acc[mi][ni], f.ah[mi], f.bh[ng][sel], f.bh[ng][sel + 1]);
        }
    #pragma unroll
    for (int mi = 0; mi < 4; ++mi)          // pass 2: Ah * Bl
        #pragma unroll
        for (int ni = 0; ni < 4; ++ni) {
            const int ng = ni >> 1, sel = (ni & 1) * 2;
            MMA16816(acc[mi][ni], f.ah[mi], f.bl[ng][sel], f.bl[ng][sel + 1]);
        }
    #pragma unroll
    for (int mi = 0; mi < 4; ++mi)          // pass 3: Al * Bh
        #pragma unroll
        for (int ni = 0; ni < 4; ++ni) {
            const int ng = ni >> 1, sel = (ni & 1) * 2;
            MMA16816(acc[mi][ni], f.al[mi], f.bh[ng][sel], f.bh[ng][sel + 1]);
        }
}

__device__ __forceinline__ void gemm_core(
    const __nv_bfloat16* __restrict__ Ah, const __nv_bfloat16* __restrict__ Al,
    const __nv_bfloat16* __restrict__ Bh, const __nv_bfloat16* __restrict__ Bl,
    float* __restrict__ Cf, __nv_bfloat16* __restrict__ Ch, __nv_bfloat16* __restrict__ Cl,
    int N, int K, int Ks, int bm, int bn)
{
    extern __shared__ __align__(1024) char smem[];
    const uint32_t sb = smem_u32(smem);

    const int tid  = threadIdx.x;
    const int lane = tid & 31;
    const int wid  = tid >> 5;

    const int wm = (wid & 1) * 64;
    const int wn = (wid >> 1) * 32;

    Loader L;
    {
        const int lrow  = tid >> 1;
        const int lhalf = (tid & 1) * 32;
        uint32_t o = (uint32_t)lrow * 64 + lhalf;
        L.d0 = sw64(o);
        L.d1 = sw64(o + 16);
        L.lhalf_elem = lhalf >> 1;
        L.pAh = Ah + (size_t)(bm + lrow) * Ks;
        L.pAl = Al + (size_t)(bm + lrow) * Ks;
        L.pBh = Bh + (size_t)(bn + lrow) * Ks;
        L.pBl = Bl + (size_t)(bn + lrow) * Ks;
    }

    const uint32_t a_base = (uint32_t)(wm + (lane & 15)) * 64 + (lane >> 4) * 16;
    const uint32_t b_base = (uint32_t)(wn + (lane & 7) + ((lane >> 4) << 3)) * 64
                          + ((lane >> 3) & 1) * 16;

    float acc[4][4][4];
    #pragma unroll
    for (int i = 0; i < 4; ++i)
        #pragma unroll
        for (int j = 0; j < 4; ++j)
            #pragma unroll
            for (int r = 0; r < 4; ++r) acc[i][j][r] = 0.0f;

    const int nk = K / BK;

    load_stage(sb, 0, L, 0);
    load_stage(sb, 1, L, BK);
    load_stage(sb, 2, L, 2 * BK);
    load_stage(sb, 3, L, 3 * BK);

    CP_ASYNC_WAIT(3);
    __syncthreads();

    Frags fa, fb;
    load_frags(fa, sb, a_base, b_base, 0);    // stage 0, k16=0

    int st = 0, stw = 4;   // current stage, write-target stage (i+4)%5
    for (int i = 0; i < nk; ++i) {
        const uint32_t stb = sb + st * STAGE_B;

        // slot A: prefetch this stage's k16=1 group, compute k16=0 group
        load_frags(fb, stb, a_base, b_base, 1);
        mma_group(acc, fa);

        // slot B: refill stage i+4, advance, prefetch next k16=0 group
        if (i + 4 < nk) load_stage(sb, stw, L, (i + 4) * BK);
        else            CP_ASYNC_COMMIT();
        CP_ASYNC_WAIT(3);
        __syncthreads();

        if (++st  == STAGES) st  = 0;
        if (++stw == STAGES) stw = 0;
        if (i + 1 < nk)
            load_frags(fa, sb + st * STAGE_B, a_base, b_base, 0);
        mma_group(acc, fb);
    }

    // ---- epilogue: fragment m16n8: (c0,c1)->row er, (c2,c3)->row er+8
    const int er = lane >> 2;
    const int ec = (lane & 3) * 2;
    #pragma unroll
    for (int mi = 0; mi < 4; ++mi)
        #pragma unroll
        for (int ni = 0; ni < 4; ++ni) {
            const int r0 = bm + wm + mi * 16 + er;
            const int c0 = bn + wn + ni * 8 + ec;
            float* a = acc[mi][ni];
            if (Cf) {
                *(float2*)(Cf + (size_t)r0 * N + c0)       = make_float2(a[0], a[1]);
                *(float2*)(Cf + (size_t)(r0 + 8) * N + c0) = make_float2(a[2], a[3]);
            } else {
                #pragma unroll
                for (int h = 0; h < 2; ++h) {
                    float v0 = a[2 * h], v1 = a[2 * h + 1];
                    __nv_bfloat16 h0 = __float2bfloat16(v0);
                    __nv_bfloat16 h1 = __float2bfloat16(v1);
                    __nv_bfloat16 l0 = __float2bfloat16(v0 - __bfloat162float(h0));
                    __nv_bfloat16 l1 = __float2bfloat16(v1 - __bfloat162float(h1));
                    size_t off = (size_t)(r0 + 8 * h) * N + c0;
                    *(__nv_bfloat162*)(Ch + off) = __halves2bfloat162(h0, h1);
                    *(__nv_bfloat162*)(Cl + off) = __halves2bfloat162(l0, l1);
                }
            }
        }
}

// Generic 2D-grid GEMM kernel (used for s = q k^T)
__global__ __launch_bounds__(256, 1)
void gemm_bf16x3(const __nv_bfloat16* __restrict__ Ah, const __nv_bfloat16* __restrict__ Al,
                 const __nv_bfloat16* __restrict__ Bh, const __nv_bfloat16* __restrict__ Bl,
                 float* __restrict__ Cf,
                 __nv_bfloat16* __restrict__ Ch, __nv_bfloat16* __restrict__ Cl,
                 int N, int K)
{
    gemm_core(Ah, Al, Bh, Bl, Cf, Ch, Cl, N, K, K, blockIdx.y * 128, blockIdx.x * 128);
}

// Merged Q/K/V projection kernel: one launch, linear grid of 1536 CTAs.
__global__ __launch_bounds__(256, 1)
void qkv_gemm(const __nv_bfloat16* __restrict__ xh,  const __nv_bfloat16* __restrict__ xl,
              const __nv_bfloat16* __restrict__ Wqh, const __nv_bfloat16* __restrict__ Wql,
              const __nv_bfloat16* __restrict__ Wkh, const __nv_bfloat16* __restrict__ Wkl,
              const __nv_bfloat16* __restrict__ Wvh, const __nv_bfloat16* __restrict__ Wvl,
              __nv_bfloat16* __restrict__ qh,  __nv_bfloat16* __restrict__ ql,
              __nv_bfloat16* __restrict__ kh,  __nv_bfloat16* __restrict__ kl,
              __nv_bfloat16* __restrict__ vTh, __nv_bfloat16* __restrict__ vTl)
{
    const int idx = blockIdx.x;
    const __nv_bfloat16 *Ah, *Al, *Bh, *Bl;
    __nv_bfloat16 *Ch, *Cl;
    int bm, bn, N;

    if (idx < 1024) {                      // Q or K: grid 16(n) x 32(m)
        const int j = idx & 511;
        bn = (j & 15) * 128;
        bm = (j >> 4) * 128;
        N  = E;
        Ah = xh; Al = xl;
        if (idx < 512) { Bh = Wqh; Bl = Wql; Ch = qh; Cl = ql; }
        else           { Bh = Wkh; Bl = Wkl; Ch = kh; Cl = kl; }
    } else {                               // vT: grid 32(n) x 16(m)
        const int j = idx - 1024;
        bn = (j & 31) * 128;
        bm = (j >> 5) * 128;
        N  = SEQ;
        Ah = Wvh; Al = Wvl; Bh = xh; Bl = xl; Ch = vTh; Cl = vTl;
    }
    gemm_core(Ah, Al, Bh, Bl, nullptr, Ch, Cl, N, E, E, bm, bn);
}

// Split-K out-GEMM: out_part[h] = w[:, h*2048:(h+1)*2048] @ vT[:, same]^T
// 1024 CTAs (6.92 waves vs 3.46 unsplit) writing disjoint fp32 partials.
__global__ __launch_bounds__(256, 1)
void out_gemm_splitk(const __nv_bfloat16* __restrict__ wh, const __nv_bfloat16* __restrict__ wl,
                     const __nv_bfloat16* __restrict__ vTh, const __nv_bfloat16* __restrict__ vTl,
                     float* __restrict__ part)   // [2][SEQ][E]
{
    const int idx = blockIdx.x;
    const int h   = idx >> 9;          // K half: 0 or 1
    const int j   = idx & 511;
    const int bn  = (j & 15) * 128;    // 16 n-tiles (E)
    const int bm  = (j >> 4) * 128;    // 32 m-tiles (SEQ)
    const int koff = h * (SEQ / 2);    // 2048-element offset within rows

    gemm_core(wh + koff, wl + koff, vTh + koff, vTl + koff,
              part + (size_t)h * SEQ * E, nullptr, nullptr,
              E, SEQ / 2, SEQ, bm, bn);
}

// Reduce the two split-K partials into the final output (float4 vectorized).
__global__ void reduce_add(const float* __restrict__ part, float* __restrict__ out, int n4)
{
    int i = blockIdx.x * blockDim.x + threadIdx.x;
    if (i >= n4) return;
    float4 a = ((const float4*)part)[i];
    float4 b = ((const float4*)part)[i + n4];
    ((float4*)out)[i] = make_float4(a.x + b.x, a.y + b.y, a.z + b.z, a.w + b.w);
}

// ---------------------------------------------------------------------------
// Merged fp32 -> (bf16 hi, bf16 lo) conversion for x, Wq, Wk, Wv (one launch)
// ---------------------------------------------------------------------------
#define X4 (SEQ * E / 4)
#define W4 (E * E / 4)

__global__ void conv_all(const float* __restrict__ x,  const float* __restrict__ Wq,
                         const float* __restrict__ Wk, const float* __restrict__ Wv,
                         __nv_bfloat16* __restrict__ xh,  __nv_bfloat16* __restrict__ xl,
                         __nv_bfloat16* __restrict__ Wqh, __nv_bfloat16* __restrict__ Wql,
                         __nv_bfloat16* __restrict__ Wkh, __nv_bfloat16* __restrict__ Wkl,
                         __nv_bfloat16* __restrict__ Wvh, __nv_bfloat16* __restrict__ Wvl)
{
    int i = blockIdx.x * blockDim.x + threadIdx.x;
    const float* src; __nv_bfloat16 *hi, *lo; int off;
    if (i < X4)                 { src = x;  hi = xh;  lo = xl;  off = i; }
    else if (i < X4 + W4)       { src = Wq; hi = Wqh; lo = Wql; off = i - X4; }
    else if (i < X4 + 2 * W4)   { src = Wk; hi = Wkh; lo = Wkl; off = i - X4 - W4; }
    else if (i < X4 + 3 * W4)   { src = Wv; hi = Wvh; lo = Wvl; off = i - X4 - 2 * W4; }
    else return;

    float4 v = ((const float4*)src)[off];
    __nv_bfloat16 h0 = __float2bfloat16(v.x), h1 = __float2bfloat16(v.y);
    __nv_bfloat16 h2 = __float2bfloat16(v.z), h3 = __float2bfloat16(v.w);
    __nv_bfloat16 l0 = __float2bfloat16(v.x - __bfloat162float(h0));
    __nv_bfloat16 l1 = __float2bfloat16(v.y - __bfloat162float(h1));
    __nv_bfloat16 l2 = __float2bfloat16(v.z - __bfloat162float(h2));
    __nv_bfloat16 l3 = __float2bfloat16(v.w - __bfloat162float(h3));
    ((__nv_bfloat162*)hi)[2 * off]     = __halves2bfloat162(h0, h1);
    ((__nv_bfloat162*)hi)[2 * off + 1] = __halves2bfloat162(h2, h3);
    ((__nv_bfloat162*)lo)[2 * off]     = __halves2bfloat162(l0, l1);
    ((__nv_bfloat162*)lo)[2 * off + 1] = __halves2bfloat162(l2, l3);
}

// ---------------------------------------------------------------------------
// Row softmax: fp32 in (float4 loads), bf16 hi/lo out, scale fused
// ---------------------------------------------------------------------------
__inline__ __device__ float warp_max(float v) {
    #pragma unroll
    for (int o = 16; o > 0; o >>= 1) v = fmaxf(v, __shfl_xor_sync(0xffffffffu, v, o));
    return v;
}
__inline__ __device__ float warp_sum(float v) {
    #pragma unroll
    for (int o = 16; o > 0; o >>= 1) v += __shfl_xor_sync(0xffffffffu, v, o);
    return v;
}

__global__ __launch_bounds__(256)
void softmax_rows(const float* __restrict__ S,
                  __nv_bfloat16* __restrict__ Wh, __nv_bfloat16* __restrict__ Wl)
{
    const int   rowi  = blockIdx.x;
    const float4* p4  = (const float4*)(S + (size_t)rowi * SEQ);
    const float scale = 0.022097086912079608f;  // 1/sqrt(2048)
    const int   tid   = threadIdx.x;
    const int   lane  = tid & 31;
    const int   wid   = tid >> 5;

    __shared__ float red[8];

    float4 v[4];
    float m = -1e30f;
    #pragma unroll
    for (int i = 0; i < 4; ++i) {
        float4 t = p4[tid + i * 256];
        v[i] = make_float4(t.x * scale, t.y * scale, t.z * scale, t.w * scale);
        m = fmaxf(m, fmaxf(fmaxf(v[i].x, v[i].y), fmaxf(v[i].z, v[i].w)));
    }
    m = warp_max(m);
    if (lane == 0) red[wid] = m;
    __syncthreads();
    if (wid == 0) {
        float t = (lane < 8) ? red[lane] : -1e30f;
        t = warp_max(t);
        if (lane == 0) red[0] = t;
    }
    __syncthreads();
    m = red[0];
    __syncthreads();

    float sum = 0.0f;
    #pragma unroll
    for (int i = 0; i < 4; ++i) {
        v[i].x = __expf(v[i].x - m);  v[i].y = __expf(v[i].y - m);
        v[i].z = __expf(v[i].z - m);  v[i].w = __expf(v[i].w - m);
        sum += (v[i].x + v[i].y) + (v[i].z + v[i].w);
    }
    sum = warp_sum(sum);
    if (lane == 0) red[wid] = sum;
    __syncthreads();
    if (wid == 0) {
        float t = (lane < 8) ? red[lane] : 0.0f;
        t = warp_sum(t);
        if (lane == 0) red[0] = t;
    }
    __syncthreads();
    const float inv = 1.0f / red[0];

    #pragma unroll
    for (int i = 0; i < 4; ++i) {
        const size_t base = (size_t)rowi * SEQ + (size_t)(tid + i * 256) * 4;
        float w0 = v[i].x * inv, w1 = v[i].y * inv, w2 = v[i].z * inv, w3 = v[i].w * inv;
        __nv_bfloat16 h0 = __float2bfloat16(w0), h1 = __float2bfloat16(w1);
        __nv_bfloat16 h2 = __float2bfloat16(w2), h3 = __float2bfloat16(w3);
        __nv_bfloat16 l0 = __float2bfloat16(w0 - __bfloat162float(h0));
        __nv_bfloat16 l1 = __float2bfloat16(w1 - __bfloat162float(h1));
        __nv_bfloat16 l2 = __float2bfloat16(w2 - __bfloat162float(h2));
        __nv_bfloat16 l3 = __float2bfloat16(w3 - __bfloat162float(h3));
        *(__nv_bfloat162*)(Wh + base)     = __halves2bfloat162(h0, h1);
        *(__nv_bfloat162*)(Wh + base + 2) = __halves2bfloat162(h2, h3);
        *(__nv_bfloat162*)(Wl + base)     = __halves2bfloat162(l0, l1);
        *(__nv_bfloat162*)(Wl + base + 2) = __halves2bfloat162(l2, l3);
    }
}

// ---------------------------------------------------------------------------
// kernel_launch
// ---------------------------------------------------------------------------
extern "C" void kernel_launch(void* const* d_in, const int* in_sizes, int n_in,
                              void* d_out, int out_size)
{
    const float* x  = (const float*)d_in[0];
    const float* Wq = (const float*)d_in[1];
    const float* Wk = (const float*)d_in[2];
    const float* Wv = (const float*)d_in[3];
    float* out = (float*)d_out;

    cudaFuncSetAttribute(gemm_bf16x3,     cudaFuncAttributeMaxDynamicSharedMemorySize, SMEM_TOTAL);
    cudaFuncSetAttribute(qkv_gemm,        cudaFuncAttributeMaxDynamicSharedMemorySize, SMEM_TOTAL);
    cudaFuncSetAttribute(out_gemm_splitk, cudaFuncAttributeMaxDynamicSharedMemorySize, SMEM_TOTAL);

    __nv_bfloat16 *xh, *xl, *Wqh, *Wql, *Wkh, *Wkl, *Wvh, *Wvl;
    __nv_bfloat16 *qh, *ql, *kh, *kl, *vTh, *vTl, *wh, *wl;
    float* s;
    cudaGetSymbolAddress((void**)&xh,  g_xh);  cudaGetSymbolAddress((void**)&xl,  g_xl);
    cudaGetSymbolAddress((void**)&Wqh, g_Wqh); cudaGetSymbolAddress((void**)&Wql, g_Wql);
    cudaGetSymbolAddress((void**)&Wkh, g_Wkh); cudaGetSymbolAddress((void**)&Wkl, g_Wkl);
    cudaGetSymbolAddress((void**)&Wvh, g_Wvh); cudaGetSymbolAddress((void**)&Wvl, g_Wvl);
    cudaGetSymbolAddress((void**)&qh,  g_qh);  cudaGetSymbolAddress((void**)&ql,  g_ql);
    cudaGetSymbolAddress((void**)&kh,  g_kh);  cudaGetSymbolAddress((void**)&kl,  g_kl);
    cudaGetSymbolAddress((void**)&vTh, g_vTh); cudaGetSymbolAddress((void**)&vTl, g_vTl);
    cudaGetSymbolAddress((void**)&wh,  g_wh);  cudaGetSymbolAddress((void**)&wl,  g_wl);
    cudaGetSymbolAddress((void**)&s,   g_s);

    // split all fp32 inputs into bf16 hi/lo in one launch
    const int total4 = X4 + 3 * W4;
    conv_all<<<(total4 + 255) / 256, 256>>>(x, Wq, Wk, Wv,
                                            xh, xl, Wqh, Wql, Wkh, Wkl, Wvh, Wvl);

    // q, k, vT in ONE launch (1536 CTAs)
    qkv_gemm<<<1536, 256, SMEM_TOTAL>>>(xh, xl, Wqh, Wql, Wkh, Wkl, Wvh, Wvl,
                                        qh, ql, kh, kl, vTh, vTl);

    // s = q @ k^T  [SEQ,SEQ] -> fp32
    gemm_bf16x3<<<dim3(SEQ / 128, SEQ / 128), 256, SMEM_TOTAL>>>(
        qh, ql, kh, kl, s, nullptr, nullptr, SEQ, E);

    // w = softmax(s/sqrt(E)) -> bf16 hi/lo   (s buffer is dead afterwards)
    softmax_rows<<<SEQ, 256>>>(s, wh, wl);

    // out = w @ vT^T via split-K: 1024 CTAs write 2 fp32 partials into g_s
    out_gemm_splitk<<<1024, 256, SMEM_TOTAL>>>(wh, wl, vTh, vTl, s);

    // final reduce: out = part0 + part1
    const int n4 = SEQ * E / 4;
    reduce_add<<<(n4 + 255) / 256, 256>>>(s, out, n4);
}